// round 3
// baseline (speedup 1.0000x reference)
#include <cuda_runtime.h>
#include <cuda_bf16.h>

// x (8,3,512,512) f32, y (8,3,1024,1024) f32, w1,b1,w2,b2 (3,) f32.
// out_lr = sigmoid(w2 * boxsum3x3_dil2(relu(w1*x+b1)) + b2) * relu(w1*x+b1)
// output = y + nearest_upsample_x2(out_lr)
//
// Sliding-window kernel: block = 512-col strip x 16 output rows.
// Each x row loaded ONCE; horizontal sums kept in a 5-deep register window,
// center activations in a 3-deep window. Output row h = hs[h-2]+hs[h]+hs[h+2].

#define HH 512
#define WW 512
#define H2 1024
#define W2 1024
#define CC 3
#define ROWS 16

__device__ __forceinline__ float actv(float v, float w1v, float b1v) {
    return fmaxf(fmaf(w1v, v, b1v), 0.0f);
}

struct RowData { float4 hs; float4 a; };

__device__ __forceinline__ RowData load_row(const float* __restrict__ xp, int r, int w0,
                                            bool okL, bool okR, float w1v, float b1v)
{
    RowData rd;
    if ((unsigned)r < (unsigned)HH) {
        const float* row = xp + (size_t)r * WW;
        float aLz = 0.f, aLw = 0.f, aR0 = 0.f, aR1 = 0.f;
        if (okL) {   // cols w0-2, w0-1
            float2 L = *reinterpret_cast<const float2*>(row + w0 - 2);
            aLz = actv(L.x, w1v, b1v);
            aLw = actv(L.y, w1v, b1v);
        }
        float4 C = *reinterpret_cast<const float4*>(row + w0);
        float a0 = actv(C.x, w1v, b1v);
        float a1 = actv(C.y, w1v, b1v);
        float a2 = actv(C.z, w1v, b1v);
        float a3 = actv(C.w, w1v, b1v);
        if (okR) {   // cols w0+4, w0+5
            float2 R = *reinterpret_cast<const float2*>(row + w0 + 4);
            aR0 = actv(R.x, w1v, b1v);
            aR1 = actv(R.y, w1v, b1v);
        }
        const float t02 = a0 + a2;
        const float t13 = a1 + a3;
        rd.hs = make_float4(aLz + t02, aLw + t13, t02 + aR0, t13 + aR1);
        rd.a  = make_float4(a0, a1, a2, a3);
    } else {
        rd.hs = make_float4(0.f, 0.f, 0.f, 0.f);
        rd.a  = rd.hs;
    }
    return rd;
}

__global__ __launch_bounds__(128)
void fused_shift_gate_up_kernel(const float* __restrict__ x,
                                const float* __restrict__ y,
                                const float* __restrict__ w1,
                                const float* __restrict__ b1,
                                const float* __restrict__ w2,
                                const float* __restrict__ b2,
                                float* __restrict__ out)
{
    const int tid   = threadIdx.x;          // 0..127
    const int w0    = tid << 2;             // low-res col base (mult of 4)
    const int h0    = blockIdx.y * ROWS;    // first output row of this block
    const int plane = blockIdx.z;           // b*C + c
    const int c     = plane % CC;

    const float w1v = __ldg(w1 + c);
    const float b1v = __ldg(b1 + c);
    const float w2v = __ldg(w2 + c);
    const float b2v = __ldg(b2 + c);

    const float* xp = x + (size_t)plane * (HH * WW);
    const bool okL = (w0 >= 2);
    const bool okR = (w0 + 5 < WW);

    // Prologue: fill the window with rows h0-2 .. h0+1
    RowData rA = load_row(xp, h0 - 2, w0, okL, okR, w1v, b1v);  // h-2
    RowData rB = load_row(xp, h0 - 1, w0, okL, okR, w1v, b1v);  // h-1
    RowData rC = load_row(xp, h0,     w0, okL, okR, w1v, b1v);  // h   (center)
    RowData rD = load_row(xp, h0 + 1, w0, okL, okR, w1v, b1v);  // h+1

    size_t ybase = (size_t)plane * ((size_t)H2 * W2)
                 + (size_t)(2 * h0) * W2 + (size_t)(2 * w0);

    #pragma unroll
    for (int i = 0; i < ROWS; ++i) {
        const int h = h0 + i;

        // Streaming y reads for the 2x8 high-res patch
        float4 ya0 = __ldcs(reinterpret_cast<const float4*>(y + ybase));
        float4 yb0 = __ldcs(reinterpret_cast<const float4*>(y + ybase + 4));
        float4 ya1 = __ldcs(reinterpret_cast<const float4*>(y + ybase + W2));
        float4 yb1 = __ldcs(reinterpret_cast<const float4*>(y + ybase + W2 + 4));

        // New bottom row h+2 (only NEW x data this iteration)
        RowData rE = load_row(xp, h + 2, w0, okL, okR, w1v, b1v);

        // Dilated 3x3 box sums for the 4 pixels
        const float s0 = rA.hs.x + rC.hs.x + rE.hs.x;
        const float s1 = rA.hs.y + rC.hs.y + rE.hs.y;
        const float s2 = rA.hs.z + rC.hs.z + rE.hs.z;
        const float s3 = rA.hs.w + rC.hs.w + rE.hs.w;

        const float o0 = rC.a.x / (1.0f + __expf(-fmaf(w2v, s0, b2v)));
        const float o1 = rC.a.y / (1.0f + __expf(-fmaf(w2v, s1, b2v)));
        const float o2 = rC.a.z / (1.0f + __expf(-fmaf(w2v, s2, b2v)));
        const float o3 = rC.a.w / (1.0f + __expf(-fmaf(w2v, s3, b2v)));

        float4 ua0 = make_float4(ya0.x + o0, ya0.y + o0, ya0.z + o1, ya0.w + o1);
        float4 ub0 = make_float4(yb0.x + o2, yb0.y + o2, yb0.z + o3, yb0.w + o3);
        float4 ua1 = make_float4(ya1.x + o0, ya1.y + o0, ya1.z + o1, ya1.w + o1);
        float4 ub1 = make_float4(yb1.x + o2, yb1.y + o2, yb1.z + o3, yb1.w + o3);

        __stcs(reinterpret_cast<float4*>(out + ybase),          ua0);
        __stcs(reinterpret_cast<float4*>(out + ybase + 4),      ub0);
        __stcs(reinterpret_cast<float4*>(out + ybase + W2),     ua1);
        __stcs(reinterpret_cast<float4*>(out + ybase + W2 + 4), ub1);

        // Slide the window (fully unrolled loop -> register renaming, no MOVs)
        rA = rB; rB = rC; rC = rD; rD = rE;
        ybase += (size_t)(2 * W2);
    }
}

extern "C" void kernel_launch(void* const* d_in, const int* in_sizes, int n_in,
                              void* d_out, int out_size)
{
    const float* x  = (const float*)d_in[0];
    const float* y  = (const float*)d_in[1];
    const float* w1 = (const float*)d_in[2];
    const float* b1 = (const float*)d_in[3];
    const float* w2 = (const float*)d_in[4];
    const float* b2 = (const float*)d_in[5];
    float* out = (float*)d_out;

    dim3 grid(1, HH / ROWS, 8 * CC);   // 32 row-chunks x 24 planes = 768 blocks
    dim3 block(128, 1, 1);             // 128 threads x 4 low-res cols = 512
    fused_shift_gate_up_kernel<<<grid, block>>>(x, y, w1, b1, w2, b2, out);
}

// round 4
// speedup vs baseline: 1.1096x; 1.1096x over previous
#include <cuda_runtime.h>
#include <cuda_bf16.h>

// x (8,3,512,512) f32, y (8,3,1024,1024) f32, w1,b1,w2,b2 (3,) f32.
// out_lr = sigmoid(w2 * boxsum3x3_dil2(relu(w1*x+b1)) + b2) * relu(w1*x+b1)
// output = y + nearest_upsample_x2(out_lr)
//
// Each thread: 4 low-res cols x 2 parity-paired rows (h, h+2).
// Rows h and h+2 share tap rows {h, h+2}: 4 x-rows loaded instead of 6.
// 12 x-loads + 8 y-loads issued independently -> high MLP per thread.

#define HH 512
#define WW 512
#define H2 1024
#define W2 1024
#define CC 3

__device__ __forceinline__ float actv(float v, float w1v, float b1v) {
    return fmaxf(fmaf(w1v, v, b1v), 0.0f);
}

struct RowData { float4 hs; float4 a; };

__device__ __forceinline__ RowData load_row(const float* __restrict__ xp, int r, int w0,
                                            bool okL, bool okR, float w1v, float b1v)
{
    RowData rd;
    if ((unsigned)r < (unsigned)HH) {
        const float* row = xp + (size_t)r * WW;
        float aLz = 0.f, aLw = 0.f, aR0 = 0.f, aR1 = 0.f;
        if (okL) {   // cols w0-2, w0-1
            float2 L = *reinterpret_cast<const float2*>(row + w0 - 2);
            aLz = actv(L.x, w1v, b1v);
            aLw = actv(L.y, w1v, b1v);
        }
        float4 C = *reinterpret_cast<const float4*>(row + w0);
        float a0 = actv(C.x, w1v, b1v);
        float a1 = actv(C.y, w1v, b1v);
        float a2 = actv(C.z, w1v, b1v);
        float a3 = actv(C.w, w1v, b1v);
        if (okR) {   // cols w0+4, w0+5
            float2 R = *reinterpret_cast<const float2*>(row + w0 + 4);
            aR0 = actv(R.x, w1v, b1v);
            aR1 = actv(R.y, w1v, b1v);
        }
        const float t02 = a0 + a2;
        const float t13 = a1 + a3;
        rd.hs = make_float4(aLz + t02, aLw + t13, t02 + aR0, t13 + aR1);
        rd.a  = make_float4(a0, a1, a2, a3);
    } else {
        rd.hs = make_float4(0.f, 0.f, 0.f, 0.f);
        rd.a  = rd.hs;
    }
    return rd;
}

__global__ __launch_bounds__(128)
void fused_shift_gate_up_kernel(const float* __restrict__ x,
                                const float* __restrict__ y,
                                const float* __restrict__ w1,
                                const float* __restrict__ b1,
                                const float* __restrict__ w2,
                                const float* __restrict__ b2,
                                float* __restrict__ out)
{
    const int tid    = threadIdx.x;            // 0..127
    const int w0     = tid << 2;               // low-res col base (mult of 4)
    const int gy     = blockIdx.y;             // 0..255
    const int group  = gy >> 1;
    const int parity = gy & 1;
    const int h      = (group << 2) + parity;  // rows handled: h, h+2
    const int plane  = blockIdx.z;             // b*C + c
    const int c      = plane % CC;

    const float w1v = __ldg(w1 + c);
    const float b1v = __ldg(b1 + c);
    const float w2v = __ldg(w2 + c);
    const float b2v = __ldg(b2 + c);

    const float* xp = x + (size_t)plane * (HH * WW);
    const bool okL = (w0 >= 2);
    const bool okR = (w0 + 5 < WW);

    // Four x tap rows: h-2, h, h+2, h+4 (12 independent loads)
    RowData rA = load_row(xp, h - 2, w0, okL, okR, w1v, b1v);
    RowData rC = load_row(xp, h,     w0, okL, okR, w1v, b1v);
    RowData rE = load_row(xp, h + 2, w0, okL, okR, w1v, b1v);
    RowData rG = load_row(xp, h + 4, w0, okL, okR, w1v, b1v);

    // y patches for output rows h (hi-res 2h,2h+1) and h+2 (hi-res 2h+4,2h+5)
    const size_t obase = (size_t)plane * ((size_t)H2 * W2);
    const size_t p0 = obase + (size_t)(2 * h) * W2 + (size_t)(2 * w0);
    const size_t p1 = p0 + W2;
    const size_t q0 = p0 + (size_t)(4 * W2);
    const size_t q1 = q0 + W2;

    float4 ya0 = __ldcs(reinterpret_cast<const float4*>(y + p0));
    float4 yb0 = __ldcs(reinterpret_cast<const float4*>(y + p0 + 4));
    float4 ya1 = __ldcs(reinterpret_cast<const float4*>(y + p1));
    float4 yb1 = __ldcs(reinterpret_cast<const float4*>(y + p1 + 4));
    float4 yc0 = __ldcs(reinterpret_cast<const float4*>(y + q0));
    float4 yd0 = __ldcs(reinterpret_cast<const float4*>(y + q0 + 4));
    float4 yc1 = __ldcs(reinterpret_cast<const float4*>(y + q1));
    float4 yd1 = __ldcs(reinterpret_cast<const float4*>(y + q1 + 4));

    // Output row h: taps A + C + E
    const float s0 = rA.hs.x + rC.hs.x + rE.hs.x;
    const float s1 = rA.hs.y + rC.hs.y + rE.hs.y;
    const float s2 = rA.hs.z + rC.hs.z + rE.hs.z;
    const float s3 = rA.hs.w + rC.hs.w + rE.hs.w;
    const float o0 = rC.a.x / (1.0f + __expf(-fmaf(w2v, s0, b2v)));
    const float o1 = rC.a.y / (1.0f + __expf(-fmaf(w2v, s1, b2v)));
    const float o2 = rC.a.z / (1.0f + __expf(-fmaf(w2v, s2, b2v)));
    const float o3 = rC.a.w / (1.0f + __expf(-fmaf(w2v, s3, b2v)));

    // Output row h+2: taps C + E + G
    const float t0 = rC.hs.x + rE.hs.x + rG.hs.x;
    const float t1 = rC.hs.y + rE.hs.y + rG.hs.y;
    const float t2 = rC.hs.z + rE.hs.z + rG.hs.z;
    const float t3 = rC.hs.w + rE.hs.w + rG.hs.w;
    const float u0 = rE.a.x / (1.0f + __expf(-fmaf(w2v, t0, b2v)));
    const float u1 = rE.a.y / (1.0f + __expf(-fmaf(w2v, t1, b2v)));
    const float u2 = rE.a.z / (1.0f + __expf(-fmaf(w2v, t2, b2v)));
    const float u3 = rE.a.w / (1.0f + __expf(-fmaf(w2v, t3, b2v)));

    float4 v;
    v = make_float4(ya0.x + o0, ya0.y + o0, ya0.z + o1, ya0.w + o1);
    __stcs(reinterpret_cast<float4*>(out + p0), v);
    v = make_float4(yb0.x + o2, yb0.y + o2, yb0.z + o3, yb0.w + o3);
    __stcs(reinterpret_cast<float4*>(out + p0 + 4), v);
    v = make_float4(ya1.x + o0, ya1.y + o0, ya1.z + o1, ya1.w + o1);
    __stcs(reinterpret_cast<float4*>(out + p1), v);
    v = make_float4(yb1.x + o2, yb1.y + o2, yb1.z + o3, yb1.w + o3);
    __stcs(reinterpret_cast<float4*>(out + p1 + 4), v);

    v = make_float4(yc0.x + u0, yc0.y + u0, yc0.z + u1, yc0.w + u1);
    __stcs(reinterpret_cast<float4*>(out + q0), v);
    v = make_float4(yd0.x + u2, yd0.y + u2, yd0.z + u3, yd0.w + u3);
    __stcs(reinterpret_cast<float4*>(out + q0 + 4), v);
    v = make_float4(yc1.x + u0, yc1.y + u0, yc1.z + u1, yc1.w + u1);
    __stcs(reinterpret_cast<float4*>(out + q1), v);
    v = make_float4(yd1.x + u2, yd1.y + u2, yd1.z + u3, yd1.w + u3);
    __stcs(reinterpret_cast<float4*>(out + q1 + 4), v);
}

extern "C" void kernel_launch(void* const* d_in, const int* in_sizes, int n_in,
                              void* d_out, int out_size)
{
    const float* x  = (const float*)d_in[0];
    const float* y  = (const float*)d_in[1];
    const float* w1 = (const float*)d_in[2];
    const float* b1 = (const float*)d_in[3];
    const float* w2 = (const float*)d_in[4];
    const float* b2 = (const float*)d_in[5];
    float* out = (float*)d_out;

    dim3 grid(1, 256, 8 * CC);   // 256 row-pairs x 24 planes = 6144 blocks
    dim3 block(128, 1, 1);       // 128 threads x 4 low-res cols = 512
    fused_shift_gate_up_kernel<<<grid, block>>>(x, y, w1, b1, w2, b2, out);
}